// round 6
// baseline (speedup 1.0000x reference)
#include <cuda_runtime.h>
#include <cstdint>
#include <cstddef>

typedef unsigned long long ull;

// ---------------- output layout (float32 concat of reference tuple) -------
#define OFF_PRED 0
#define OFF_CAPS 4960000
#define OFF_DLEN 4960512
#define OFF_ALPH 4960528
#define OFF_SORT 5057744

#define NBLK 148
#define NA   96      // group-A blocks (attention path)
#define NB   52      // group-B blocks (vocab projection)

// ---------------- device scratch (static globals: no allocs) --------------
__device__ int   g_sort[16], g_dlen[16], g_caps[512];
__device__ float g_mean[16 * 1024];
__device__ float g_att1[3136 * 1024];     // 12.8 MB
__device__ float g_h[16 * 512], g_c[16 * 512];
__device__ float g_hT[512 * 16];          // h_new transposed [d][b]
__device__ float g_xT[2048 * 16];         // X transposed [k][b]: emb|awe|h
__device__ float g_att2[16 * 1024], g_gate[16 * 1024];
__device__ float g_att[3136];
__device__ unsigned g_cnt = 0, g_gen = 0;       // full barrier (+ setup)
__device__ unsigned g_cntA = 0, g_genA = 0;     // partial (96-block) barrier

// ---------------- helpers ----------------
__device__ __forceinline__ ull pk(float x, float y) {
    ull u; asm("mov.b64 %0,{%1,%2};" : "=l"(u) : "f"(x), "f"(y)); return u;
}
__device__ __forceinline__ float2 upk(ull u) {
    float2 v; asm("mov.b64 {%0,%1},%2;" : "=f"(v.x), "=f"(v.y) : "l"(u)); return v;
}
__device__ __forceinline__ ull f2(ull a, ull b, ull c) {
    ull d; asm("fma.rn.f32x2 %0,%1,%2,%3;" : "=l"(d) : "l"(a), "l"(b), "l"(c)); return d;
}
__device__ __forceinline__ ull addf2(ull a, ull b) {
    ull d; asm("add.rn.f32x2 %0,%1,%2;" : "=l"(d) : "l"(a), "l"(b)); return d;
}
__device__ __forceinline__ float sigmf(float x) { return 1.f / (1.f + expf(-x)); }

__device__ __forceinline__ void bar_sync(unsigned* cnt, unsigned* gen,
                                         unsigned count, unsigned& mygen) {
    __syncthreads();
    if (threadIdx.x == 0) {
        __threadfence();
        if (atomicAdd(cnt, 1u) == count - 1) {
            *cnt = 0;
            __threadfence();
            *(volatile unsigned*)gen = mygen + 1;
        } else {
            while (*(volatile unsigned*)gen == mygen) { }
            __threadfence();
        }
    }
    mygen++;
    __syncthreads();
}

// ================= fused setup kernel (64 blocks) ==========================
// sort+caps -> bar -> mean -> bar -> h0/c0
__global__ void __launch_bounds__(256)
ksetup(const int* __restrict__ caps_in, const int* __restrict__ clen,
       const float* __restrict__ enc,
       const float* __restrict__ ihW, const float* __restrict__ ihB,
       const float* __restrict__ icW, const float* __restrict__ icB,
       float* __restrict__ out) {
    int tid = threadIdx.x, bid = blockIdx.x;
    unsigned mygen = *(volatile unsigned*)&g_gen;
    if (bid == 0) {
        if (tid == 0) {
            int len[16];
            #pragma unroll
            for (int i = 0; i < 16; i++) len[i] = clen[i];
            for (int i = 0; i < 16; i++) {
                int rank = 0;
                for (int j = 0; j < 16; j++)
                    rank += (len[j] > len[i]) || (len[j] == len[i] && j < i);
                g_sort[rank] = i;
                g_dlen[rank] = len[i] - 1;
                out[OFF_SORT + rank] = (float)i;
                out[OFF_DLEN + rank] = (float)(len[i] - 1);
            }
        }
        __syncthreads();
        for (int j = tid; j < 512; j += 256) {
            int b = j >> 5, l = j & 31;
            int v = caps_in[g_sort[b] * 32 + l];
            g_caps[j] = v;
            out[OFF_CAPS + j] = (float)v;
        }
    }
    bar_sync(&g_cnt, &g_gen, 64, mygen);
    // mean over P
    {
        int j = bid * 256 + tid;    // 16384
        int b = j >> 10, e = j & 1023;
        const float* p0 = enc + ((size_t)g_sort[b] * 196) * 1024 + e;
        float s = 0.f;
        #pragma unroll 8
        for (int p = 0; p < 196; p++) s += p0[(size_t)p * 1024];
        g_mean[j] = s * (1.0f / 196.0f);
    }
    bar_sync(&g_cnt, &g_gen, 64, mygen);
    // h0 / c0
    {
        int j = bid * 256 + tid;    // 16384 = 2 x 16 x 512
        int which = j >> 13;
        int jj = j & 8191;
        int b = jj >> 9, d = jj & 511;
        const float* W = which ? icW : ihW;
        const float* mrow = g_mean + b * 1024;
        float acc = 0.f;
        #pragma unroll 8
        for (int k = 0; k < 1024; k++) acc += mrow[k] * W[k * 512 + d];
        float val = acc + (which ? icB[d] : ihB[d]);
        if (which) g_c[b * 512 + d] = val;
        else { g_h[b * 512 + d] = val; g_xT[(1536 + d) * 16 + b] = val; }
    }
}

// ================= att1 GEMM (unchanged) ===================================
__global__ void __launch_bounds__(256, 1)
katt1(const float* __restrict__ enc, const float* __restrict__ W,
      const float* __restrict__ bias) {
    __shared__ float As[32][132];
    __shared__ float Bs[32][128];
    int tid = threadIdx.x;
    int bm = blockIdx.y, bn = blockIdx.x;

    int kq = tid & 7, ml = tid >> 3;
    const float* arow[4];
    #pragma unroll
    for (int ps = 0; ps < 4; ps++) {
        int m = bm * 128 + ml + ps * 32;
        int mc = m < 3135 ? m : 3135;
        int b = mc / 196, p = mc - b * 196;
        arow[ps] = enc + ((size_t)g_sort[b] * 196 + p) * 1024 + kq * 4;
    }
    int nb = tid & 31, kb = tid >> 5;
    const float* bptr = W + (size_t)kb * 1024 + bn * 128 + nb * 4;

    ull acc[8][4];
    #pragma unroll
    for (int i = 0; i < 8; i++)
        #pragma unroll
        for (int j = 0; j < 4; j++) acc[i][j] = 0ull;

    int tx = tid & 15, ty = tid >> 4;

    float4 ra[4], rb[4];
    #pragma unroll
    for (int ps = 0; ps < 4; ps++) ra[ps] = *(const float4*)(arow[ps]);
    #pragma unroll
    for (int ps = 0; ps < 4; ps++) rb[ps] = *(const float4*)(bptr + (size_t)(ps * 8) * 1024);

    for (int kt = 0; kt < 1024; kt += 32) {
        #pragma unroll
        for (int ps = 0; ps < 4; ps++) {
            int mm = ml + ps * 32;
            As[kq * 4 + 0][mm] = ra[ps].x;
            As[kq * 4 + 1][mm] = ra[ps].y;
            As[kq * 4 + 2][mm] = ra[ps].z;
            As[kq * 4 + 3][mm] = ra[ps].w;
        }
        #pragma unroll
        for (int ps = 0; ps < 4; ps++)
            *(float4*)&Bs[kb + ps * 8][nb * 4] = rb[ps];
        __syncthreads();
        if (kt + 32 < 1024) {
            #pragma unroll
            for (int ps = 0; ps < 4; ps++)
                ra[ps] = *(const float4*)(arow[ps] + kt + 32);
            #pragma unroll
            for (int ps = 0; ps < 4; ps++)
                rb[ps] = *(const float4*)(bptr + (size_t)(kt + 32 + ps * 8) * 1024);
        }
        #pragma unroll 8
        for (int kk = 0; kk < 32; kk++) {
            float4 a0 = *(const float4*)&As[kk][ty * 8];
            float4 a1 = *(const float4*)&As[kk][ty * 8 + 4];
            ulonglong2 b0 = *(const ulonglong2*)&Bs[kk][tx * 8];
            ulonglong2 b1 = *(const ulonglong2*)&Bs[kk][tx * 8 + 4];
            float a[8] = {a0.x, a0.y, a0.z, a0.w, a1.x, a1.y, a1.z, a1.w};
            #pragma unroll
            for (int i = 0; i < 8; i++) {
                ull ap = pk(a[i], a[i]);
                acc[i][0] = f2(ap, b0.x, acc[i][0]);
                acc[i][1] = f2(ap, b0.y, acc[i][1]);
                acc[i][2] = f2(ap, b1.x, acc[i][2]);
                acc[i][3] = f2(ap, b1.y, acc[i][3]);
            }
        }
        __syncthreads();
    }
    int n0 = bn * 128 + tx * 8;
    float bb[8];
    #pragma unroll
    for (int j = 0; j < 8; j++) bb[j] = bias[n0 + j];
    #pragma unroll
    for (int i = 0; i < 8; i++) {
        int m = bm * 128 + ty * 8 + i;
        if (m < 3136) {
            float* dst = g_att1 + (size_t)m * 1024 + n0;
            #pragma unroll
            for (int j = 0; j < 4; j++) {
                float2 v = upk(acc[i][j]);
                dst[2 * j + 0] = v.x + bb[2 * j + 0];
                dst[2 * j + 1] = v.y + bb[2 * j + 1];
            }
        }
    }
}

// ================= persistent step kernel ==================================
__global__ void __launch_bounds__(256, 1)
kstep(const float* __restrict__ enc,
      const float* __restrict__ decW, const float* __restrict__ decB,
      const float* __restrict__ fullW, const float* __restrict__ fullB,
      const float* __restrict__ fbW, const float* __restrict__ fbB,
      const float* __restrict__ emb,
      const float* __restrict__ Wih, const float* __restrict__ bih,
      const float* __restrict__ Whh, const float* __restrict__ bhh,
      const float* __restrict__ fcW, const float* __restrict__ fcB,
      float* __restrict__ out)
{
    __shared__ ull sb8[4096];           // 32KB, reused per phase
    float* sbuf = (float*)sb8;
    const int tid = threadIdx.x;
    const int bid = blockIdx.x;
    const int lane = tid & 31;
    const int wrp  = tid >> 5;
    unsigned mygen  = *(volatile unsigned*)&g_gen;
    unsigned mygenA = *(volatile unsigned*)&g_genA;

    // -------- phase E: vocab projection for step tp (reads g_hT) ----------
    auto phaseE = [&](int tp, int start, int stride) {
        for (int ch = start; ch < 79; ch += stride) {
            int v0 = ch * 128;
            int vcol = v0 + lane * 4;
            ull acc[4][8];
            #pragma unroll
            for (int c = 0; c < 4; c++)
                #pragma unroll
                for (int j = 0; j < 8; j++) acc[c][j] = 0ull;
            if (vcol < 10000) {
                const float* wp = fcW + (size_t)(wrp * 64) * 10000 + vcol;
                const float* xb = g_hT + (wrp * 64) * 16;
                #pragma unroll 4
                for (int i = 0; i < 64; i++) {
                    float4 w4 = *(const float4*)(wp + (size_t)i * 10000);
                    const ulonglong2* xr = (const ulonglong2*)(xb + i * 16);
                    ulonglong2 x0 = xr[0], x1 = xr[1], x2 = xr[2], x3 = xr[3];
                    ull xv[8] = {x0.x, x0.y, x1.x, x1.y, x2.x, x2.y, x3.x, x3.y};
                    float wf[4] = {w4.x, w4.y, w4.z, w4.w};
                    #pragma unroll
                    for (int c = 0; c < 4; c++) {
                        ull wb = pk(wf[c], wf[c]);
                        #pragma unroll
                        for (int j = 0; j < 8; j++)
                            acc[c][j] = f2(xv[j], wb, acc[c][j]);
                    }
                }
            }
            ull* s = sb8;
            if (wrp < 4) {
                #pragma unroll
                for (int c = 0; c < 4; c++)
                    #pragma unroll
                    for (int j = 0; j < 8; j++)
                        s[(((wrp) * 32 + lane) * 4 + c) * 8 + j] = acc[c][j];
            }
            __syncthreads();
            if (wrp >= 4) {
                int p = wrp - 4;
                #pragma unroll
                for (int c = 0; c < 4; c++)
                    #pragma unroll
                    for (int j = 0; j < 8; j++) {
                        int idx = (((p) * 32 + lane) * 4 + c) * 8 + j;
                        s[idx] = addf2(s[idx], acc[c][j]);
                    }
            }
            __syncthreads();
            #pragma unroll
            for (int q = 0; q < 4; q++) {
                int o = q * 256 + tid;
                int col = o & 127, bp = o >> 7;
                int v = v0 + col;
                if (v < 10000) {
                    int cg = col >> 2, cc = col & 3;
                    ull sm = s[((0 * 32 + cg) * 4 + cc) * 8 + bp];
                    sm = addf2(sm, s[((1 * 32 + cg) * 4 + cc) * 8 + bp]);
                    sm = addf2(sm, s[((2 * 32 + cg) * 4 + cc) * 8 + bp]);
                    sm = addf2(sm, s[((3 * 32 + cg) * 4 + cc) * 8 + bp]);
                    float2 r = upk(sm);
                    float fb = fcB[v];
                    int b0 = 2 * bp, b1 = b0 + 1;
                    out[OFF_PRED + (size_t)(b0 * 31 + tp) * 10000 + v] =
                        (g_dlen[b0] > tp) ? (r.x + fb) : 0.f;
                    out[OFF_PRED + (size_t)(b1 * 31 + tp) * 10000 + v] =
                        (g_dlen[b1] > tp) ? (r.y + fb) : 0.f;
                }
            }
            __syncthreads();
        }
    };

    for (int t = 0; t < 31; t++) {
        if (bid < NA) {
            // ====== Segment 1: A1 (blocks 0-63) + emb fill (64-95) ========
            if (bid < 64) {
                int cg = tid & 7, ks = tid >> 3;
                int c0 = bid * 32;
                int colg = c0 + cg * 4;
                const float* wp = (colg < 1024)
                    ? (decW + (size_t)(ks * 16) * 1024 + colg)
                    : (fbW + (size_t)(ks * 16) * 1024 + (colg - 1024));
                const float* xb = g_xT + (1536 + ks * 16) * 16;
                ull acc[4][8];
                #pragma unroll
                for (int c = 0; c < 4; c++)
                    #pragma unroll
                    for (int j = 0; j < 8; j++) acc[c][j] = 0ull;
                #pragma unroll 4
                for (int i = 0; i < 16; i++) {
                    float4 w4 = *(const float4*)(wp + (size_t)i * 1024);
                    const ulonglong2* xr = (const ulonglong2*)(xb + i * 16);
                    ulonglong2 x0 = xr[0], x1 = xr[1], x2 = xr[2], x3 = xr[3];
                    ull xv[8] = {x0.x, x0.y, x1.x, x1.y, x2.x, x2.y, x3.x, x3.y};
                    float wf[4] = {w4.x, w4.y, w4.z, w4.w};
                    #pragma unroll
                    for (int c = 0; c < 4; c++) {
                        ull wb = pk(wf[c], wf[c]);
                        #pragma unroll
                        for (int j = 0; j < 8; j++)
                            acc[c][j] = f2(xv[j], wb, acc[c][j]);
                    }
                }
                #pragma unroll
                for (int c = 0; c < 4; c++)
                    #pragma unroll
                    for (int j = 0; j < 8; j++) {
                        acc[c][j] = addf2(acc[c][j],
                            __shfl_xor_sync(0xffffffffu, acc[c][j], 8));
                        acc[c][j] = addf2(acc[c][j],
                            __shfl_xor_sync(0xffffffffu, acc[c][j], 16));
                    }
                if (lane < 8) {
                    #pragma unroll
                    for (int c = 0; c < 4; c++)
                        #pragma unroll
                        for (int j = 0; j < 8; j++)
                            sb8[(((wrp) * 8 + lane) * 4 + c) * 8 + j] = acc[c][j];
                }
                __syncthreads();
                {
                    int col = tid >> 3, bp = tid & 7;
                    int cg2 = col >> 2, cc = col & 3;
                    ull sm = sb8[((0 * 8 + cg2) * 4 + cc) * 8 + bp];
                    #pragma unroll
                    for (int w = 1; w < 8; w++)
                        sm = addf2(sm, sb8[((w * 8 + cg2) * 4 + cc) * 8 + bp]);
                    float2 r = upk(sm);
                    int ocol = c0 + col;
                    int b0 = 2 * bp, b1 = b0 + 1;
                    if (ocol < 1024) {
                        float db = decB[ocol];
                        g_att2[b0 * 1024 + ocol] = r.x + db;
                        g_att2[b1 * 1024 + ocol] = r.y + db;
                    } else {
                        int oc = ocol - 1024;
                        float fb = fbB[oc];
                        g_gate[b0 * 1024 + oc] = sigmf(r.x + fb);
                        g_gate[b1 * 1024 + oc] = sigmf(r.y + fb);
                    }
                }
            } else {
                // emb fill: blocks 64..95, 1 elem per thread (8192 total)
                int j = (bid - 64) * 256 + tid;
                int b = j >> 9, k = j & 511;
                int tok = g_caps[b * 32 + t];
                g_xT[k * 16 + b] = emb[(size_t)tok * 512 + k];
            }
            bar_sync(&g_cntA, &g_genA, NA, mygenA);

            // ====== Segment 2: scores on 96 blocks (6 slices/batch) =======
            {
                const int sst[6] = {0, 33, 66, 99, 132, 164};
                const int scn[6] = {33, 33, 33, 33, 32, 32};
                int b = bid / 6, sl = bid % 6;
                float* s_att2 = sbuf;            // 1024
                float* s_fw   = sbuf + 1024;     // 1024
                for (int j = tid; j < 1024; j += 256) {
                    s_att2[j] = g_att2[b * 1024 + j];
                    s_fw[j]   = fullW[j];
                }
                __syncthreads();
                float fb0 = fullB[0];
                int p0 = sst[sl], np = scn[sl];
                for (int pi = wrp; pi < np; pi += 8) {
                    int p = p0 + pi;
                    const float* row = g_att1 + (size_t)(b * 196 + p) * 1024;
                    float acc = 0.f;
                    #pragma unroll
                    for (int eq = 0; eq < 8; eq++) {
                        int e = eq * 128 + lane * 4;
                        float4 x  = *(const float4*)(row + e);
                        float4 a2 = *(const float4*)&s_att2[e];
                        float4 w  = *(const float4*)&s_fw[e];
                        acc += fmaxf(x.x + a2.x, 0.f) * w.x;
                        acc += fmaxf(x.y + a2.y, 0.f) * w.y;
                        acc += fmaxf(x.z + a2.z, 0.f) * w.z;
                        acc += fmaxf(x.w + a2.w, 0.f) * w.w;
                    }
                    #pragma unroll
                    for (int o = 16; o > 0; o >>= 1)
                        acc += __shfl_xor_sync(0xffffffffu, acc, o);
                    if (lane == 0) g_att[b * 196 + p] = acc + fb0;
                }
            }
            bar_sync(&g_cntA, &g_genA, NA, mygenA);

            // ====== Segment 3: softmax + alphas + awe on 64 blocks ========
            if (bid < 64) {
                float* s_al = sbuf;            // 200
                float* s_rd = sbuf + 256;      // 8
                float* s_sc = sbuf + 288;      // 1
                int b = bid >> 2, ec = bid & 3;
                float sc = (tid < 196) ? g_att[b * 196 + tid] : -1e30f;
                float v = sc;
                #pragma unroll
                for (int o = 16; o > 0; o >>= 1)
                    v = fmaxf(v, __shfl_xor_sync(0xffffffffu, v, o));
                if (lane == 0) s_rd[wrp] = v;
                __syncthreads();
                if (tid == 0) {
                    float m = s_rd[0];
                    #pragma unroll
                    for (int i = 1; i < 8; i++) m = fmaxf(m, s_rd[i]);
                    s_sc[0] = m;
                }
                __syncthreads();
                float ex = (tid < 196) ? expf(sc - s_sc[0]) : 0.f;
                v = ex;
                #pragma unroll
                for (int o = 16; o > 0; o >>= 1)
                    v += __shfl_xor_sync(0xffffffffu, v, o);
                if (lane == 0) s_rd[wrp] = v;
                __syncthreads();
                if (tid == 0) {
                    float s = 0.f;
                    #pragma unroll
                    for (int i = 0; i < 8; i++) s += s_rd[i];
                    s_sc[0] = 1.0f / s;
                }
                __syncthreads();
                float alpha = ex * s_sc[0];
                bool act = g_dlen[b] > t;
                if (tid < 196) {
                    s_al[tid] = alpha;
                    if (ec == 0)
                        out[OFF_ALPH + (size_t)(b * 31 + t) * 196 + tid] =
                            act ? alpha : 0.f;
                }
                __syncthreads();
                int el = tid;                  // 256 threads x 1 float4
                int e4 = ec * 1024 + el * 4;   // wait: 256*4 = 1024 per block
                const float* ep = enc + ((size_t)g_sort[b] * 196) * 1024 + (ec * 256 * 0);
                // each block covers e-range [ec*256 .. ec*256+255] via 64 thr? No:
                // 256 threads x 1 e each -> e = ec*256 + tid
                (void)ep; (void)e4; (void)el;
                int e = ec * 256 + tid;
                const float* ep2 = enc + ((size_t)g_sort[b] * 196) * 1024 + e;
                float acc = 0.f;
                #pragma unroll 14
                for (int p = 0; p < 196; p++)
                    acc += s_al[p] * ep2[(size_t)p * 1024];
                g_xT[(512 + e) * 16 + b] = acc + g_gate[b * 1024 + e];
            }
        } else {
            // ---------- group B: vocab projection for t-1 -----------------
            if (t > 0) phaseE(t - 1, bid - NA, NB);
        }
        bar_sync(&g_cnt, &g_gen, NBLK, mygen);

        // ============ fused LSTM gates GEMM + elementwise =================
        if (bid < 128) {
            int d0 = bid * 4;
            int cg = tid & 3, ks = tid >> 2;
            int col = cg * 512 + d0;
            const float* wp = (ks < 48)
                ? (Wih + (size_t)(ks * 32) * 2048 + col)
                : (Whh + (size_t)((ks - 48) * 32) * 2048 + col);
            const float* xb = g_xT + (ks * 32) * 16;
            ull acc[4][8];
            #pragma unroll
            for (int c = 0; c < 4; c++)
                #pragma unroll
                for (int j = 0; j < 8; j++) acc[c][j] = 0ull;
            #pragma unroll 4
            for (int i = 0; i < 32; i++) {
                float4 w4 = *(const float4*)(wp + (size_t)i * 2048);
                const ulonglong2* xr = (const ulonglong2*)(xb + i * 16);
                ulonglong2 x0 = xr[0], x1 = xr[1], x2 = xr[2], x3 = xr[3];
                ull xv[8] = {x0.x, x0.y, x1.x, x1.y, x2.x, x2.y, x3.x, x3.y};
                float wf[4] = {w4.x, w4.y, w4.z, w4.w};
                #pragma unroll
                for (int c = 0; c < 4; c++) {
                    ull wb = pk(wf[c], wf[c]);
                    #pragma unroll
                    for (int j = 0; j < 8; j++)
                        acc[c][j] = f2(xv[j], wb, acc[c][j]);
                }
            }
            #pragma unroll
            for (int c = 0; c < 4; c++)
                #pragma unroll
                for (int j = 0; j < 8; j++) {
                    acc[c][j] = addf2(acc[c][j],
                        __shfl_xor_sync(0xffffffffu, acc[c][j], 4));
                    acc[c][j] = addf2(acc[c][j],
                        __shfl_xor_sync(0xffffffffu, acc[c][j], 8));
                    acc[c][j] = addf2(acc[c][j],
                        __shfl_xor_sync(0xffffffffu, acc[c][j], 16));
                }
            if (lane < 4) {
                #pragma unroll
                for (int c = 0; c < 4; c++)
                    #pragma unroll
                    for (int j = 0; j < 8; j++)
                        sb8[(((wrp) * 4 + lane) * 4 + c) * 8 + j] = acc[c][j];
            }
            float* s_gt = (float*)(sb8 + 1024);   // [16][16]
            __syncthreads();
            if (tid < 128) {
                int c = tid >> 3, bp = tid & 7;
                int g = c >> 2, dd = c & 3;
                ull sm = sb8[((0 * 4 + g) * 4 + dd) * 8 + bp];
                #pragma unroll
                for (int w = 1; w < 8; w++)
                    sm = addf2(sm, sb8[((w * 4 + g) * 4 + dd) * 8 + bp]);
                float2 r = upk(sm);
                int col2 = g * 512 + d0 + dd;
                float bb = bih[col2] + bhh[col2];
                s_gt[c * 16 + 2 * bp + 0] = r.x + bb;
                s_gt[c * 16 + 2 * bp + 1] = r.y + bb;
            }
            __syncthreads();
            if (tid < 64) {
                int dd2 = tid >> 4, b = tid & 15;
                int d = d0 + dd2;
                float gi = s_gt[(0 + dd2) * 16 + b];
                float gf = s_gt[(4 + dd2) * 16 + b];
                float gc = s_gt[(8 + dd2) * 16 + b];
                float go = s_gt[(12 + dd2) * 16 + b];
                int gid = b * 512 + d;
                float cold = g_c[gid];
                float cnew = sigmf(gf) * cold + sigmf(gi) * tanhf(gc);
                float hnew = sigmf(go) * tanhf(cnew);
                bool act = g_dlen[b] > t;
                float h2 = act ? hnew : g_h[gid];
                float c2v = act ? cnew : cold;
                g_h[gid] = h2;
                g_c[gid] = c2v;
                g_hT[d * 16 + b] = hnew;
                g_xT[(1536 + d) * 16 + b] = h2;
            }
        }
        bar_sync(&g_cnt, &g_gen, NBLK, mygen);
    }

    // final vocab projection for t = 30 on all blocks
    phaseE(30, bid, NBLK);
}

// ================= launcher ==============================================
extern "C" void kernel_launch(void* const* d_in, const int* in_sizes, int n_in,
                              void* d_out, int out_size) {
    const float* enc    = (const float*)d_in[0];
    const float* encW   = (const float*)d_in[1];
    const float* encB   = (const float*)d_in[2];
    const float* decW   = (const float*)d_in[3];
    const float* decB   = (const float*)d_in[4];
    const float* fullW  = (const float*)d_in[5];
    const float* fullB  = (const float*)d_in[6];
    const float* emb    = (const float*)d_in[7];
    const float* Wih    = (const float*)d_in[8];
    const float* bih    = (const float*)d_in[9];
    const float* Whh    = (const float*)d_in[10];
    const float* bhh    = (const float*)d_in[11];
    const float* ihW    = (const float*)d_in[12];
    const float* ihB    = (const float*)d_in[13];
    const float* icW    = (const float*)d_in[14];
    const float* icB    = (const float*)d_in[15];
    const float* fbW    = (const float*)d_in[16];
    const float* fbB    = (const float*)d_in[17];
    const float* fcW    = (const float*)d_in[18];
    const float* fcB    = (const float*)d_in[19];
    const int*   capsin = (const int*)d_in[20];
    const int*   clen   = (const int*)d_in[21];
    float* out = (float*)d_out;

    ksetup<<<64, 256>>>(capsin, clen, enc, ihW, ihB, icW, icB, out);
    katt1<<<dim3(8, 25), 256>>>(enc, encW, encB);
    kstep<<<NBLK, 256>>>(enc, decW, decB, fullW, fullB, fbW, fbB, emb,
                         Wih, bih, Whh, bhh, fcW, fcB, out);
}

// round 11
// speedup vs baseline: 1.0661x; 1.0661x over previous
#include <cuda_runtime.h>
#include <cstdint>
#include <cstddef>

typedef unsigned long long ull;

// ---------------- output layout (float32 concat of reference tuple) -------
#define OFF_PRED 0
#define OFF_CAPS 4960000
#define OFF_DLEN 4960512
#define OFF_ALPH 4960528
#define OFF_SORT 5057744

#define NBLK 148

// ---------------- device scratch (static globals: no allocs) --------------
__device__ float g_att1[3136 * 1024];     // 12.8 MB
__device__ float g_h[16 * 512], g_c[16 * 512];
__device__ float g_hT[512 * 16];          // h_new transposed [d][b]
__device__ float g_xT[2048 * 16];         // X transposed [k][b]: emb|awe|h
__device__ float g_att2[16 * 1024], g_gate[16 * 1024];
__device__ unsigned g_cnt = 0, g_gen = 0;       // full barrier
__device__ unsigned g_cntA = 0, g_genA = 0;     // partial (64-block) barrier

// ---------------- helpers ----------------
__device__ __forceinline__ ull pk(float x, float y) {
    ull u; asm("mov.b64 %0,{%1,%2};" : "=l"(u) : "f"(x), "f"(y)); return u;
}
__device__ __forceinline__ float2 upk(ull u) {
    float2 v; asm("mov.b64 {%0,%1},%2;" : "=f"(v.x), "=f"(v.y) : "l"(u)); return v;
}
__device__ __forceinline__ ull f2(ull a, ull b, ull c) {
    ull d; asm("fma.rn.f32x2 %0,%1,%2,%3;" : "=l"(d) : "l"(a), "l"(b), "l"(c)); return d;
}
__device__ __forceinline__ ull addf2(ull a, ull b) {
    ull d; asm("add.rn.f32x2 %0,%1,%2;" : "=l"(d) : "l"(a), "l"(b)); return d;
}
__device__ __forceinline__ float sigmf(float x) { return 1.f / (1.f + expf(-x)); }

__device__ __forceinline__ void bar_sync(unsigned* cnt, unsigned* gen,
                                         unsigned count, unsigned& mygen) {
    __syncthreads();
    if (threadIdx.x == 0) {
        __threadfence();
        if (atomicAdd(cnt, 1u) == count - 1) {
            *cnt = 0;
            __threadfence();
            *(volatile unsigned*)gen = mygen + 1;
        } else {
            while (*(volatile unsigned*)gen == mygen) { }
            __threadfence();
        }
    }
    mygen++;
    __syncthreads();
}

// local stable-descending sort of lengths; fills s_sort/s_dlen in smem.
// call with >= 16 active threads; follows with __syncthreads by caller.
__device__ __forceinline__ void local_sort(const int* __restrict__ clen,
                                           int* s_sort, int* s_dlen) {
    int tid = threadIdx.x;
    if (tid < 16) {
        int li = clen[tid];
        int rank = 0;
        #pragma unroll
        for (int j = 0; j < 16; j++) {
            int lj = clen[j];
            rank += (lj > li) || (lj == li && j < tid);
        }
        s_sort[rank] = tid;
        s_dlen[rank] = li - 1;
    }
}

// ================= att1 GEMM + embedded setup blocks =======================
// grid (8, 26): rows 0..24 = GEMM tiles; row 25 = mean + h0/c0 (8 blocks)
__global__ void __launch_bounds__(256, 1)
katt1(const float* __restrict__ enc, const float* __restrict__ W,
      const float* __restrict__ bias,
      const float* __restrict__ ihW, const float* __restrict__ ihB,
      const float* __restrict__ icW, const float* __restrict__ icB,
      const int* __restrict__ clen) {
    __shared__ float As[32][132];
    __shared__ float Bs[32][128];
    __shared__ int s_sort[16], s_dlen[16];
    int tid = threadIdx.x;
    int bm = blockIdx.y, bn = blockIdx.x;

    local_sort(clen, s_sort, s_dlen);
    __syncthreads();

    if (bm == 25) {
        // -------- setup block: mean + h0/c0 for 2 batches ----------------
        float* smean = (float*)As;    // 2048 floats
        #pragma unroll 1
        for (int j = tid; j < 2048; j += 256) {
            int bb = j >> 10, e = j & 1023;
            int batch = bn * 2 + bb;
            const float* p0 = enc + ((size_t)s_sort[batch] * 196) * 1024 + e;
            float s = 0.f;
            #pragma unroll 8
            for (int p = 0; p < 196; p++) s += p0[(size_t)p * 1024];
            smean[j] = s * (1.0f / 196.0f);
        }
        __syncthreads();
        #pragma unroll 1
        for (int j = tid; j < 2048; j += 256) {
            int bb = j >> 10;
            int rest = j & 1023;
            int which = rest >> 9, d = rest & 511;
            int batch = bn * 2 + bb;
            const float* Wm = which ? icW : ihW;
            const float* mrow = smean + bb * 1024;
            float acc = 0.f;
            #pragma unroll 8
            for (int k = 0; k < 1024; k++) acc += mrow[k] * Wm[k * 512 + d];
            float val = acc + (which ? icB[d] : ihB[d]);
            if (which) g_c[batch * 512 + d] = val;
            else { g_h[batch * 512 + d] = val; g_xT[(1536 + d) * 16 + batch] = val; }
        }
        return;
    }

    int kq = tid & 7, ml = tid >> 3;
    const float* arow[4];
    #pragma unroll
    for (int ps = 0; ps < 4; ps++) {
        int m = bm * 128 + ml + ps * 32;
        int mc = m < 3135 ? m : 3135;
        int b = mc / 196, p = mc - b * 196;
        arow[ps] = enc + ((size_t)s_sort[b] * 196 + p) * 1024 + kq * 4;
    }
    int nb = tid & 31, kb = tid >> 5;
    const float* bptr = W + (size_t)kb * 1024 + bn * 128 + nb * 4;

    ull acc[8][4];
    #pragma unroll
    for (int i = 0; i < 8; i++)
        #pragma unroll
        for (int j = 0; j < 4; j++) acc[i][j] = 0ull;

    int tx = tid & 15, ty = tid >> 4;

    float4 ra[4], rb[4];
    #pragma unroll
    for (int ps = 0; ps < 4; ps++) ra[ps] = *(const float4*)(arow[ps]);
    #pragma unroll
    for (int ps = 0; ps < 4; ps++) rb[ps] = *(const float4*)(bptr + (size_t)(ps * 8) * 1024);

    for (int kt = 0; kt < 1024; kt += 32) {
        #pragma unroll
        for (int ps = 0; ps < 4; ps++) {
            int mm = ml + ps * 32;
            As[kq * 4 + 0][mm] = ra[ps].x;
            As[kq * 4 + 1][mm] = ra[ps].y;
            As[kq * 4 + 2][mm] = ra[ps].z;
            As[kq * 4 + 3][mm] = ra[ps].w;
        }
        #pragma unroll
        for (int ps = 0; ps < 4; ps++)
            *(float4*)&Bs[kb + ps * 8][nb * 4] = rb[ps];
        __syncthreads();
        if (kt + 32 < 1024) {
            #pragma unroll
            for (int ps = 0; ps < 4; ps++)
                ra[ps] = *(const float4*)(arow[ps] + kt + 32);
            #pragma unroll
            for (int ps = 0; ps < 4; ps++)
                rb[ps] = *(const float4*)(bptr + (size_t)(kt + 32 + ps * 8) * 1024);
        }
        #pragma unroll 8
        for (int kk = 0; kk < 32; kk++) {
            float4 a0 = *(const float4*)&As[kk][ty * 8];
            float4 a1 = *(const float4*)&As[kk][ty * 8 + 4];
            ulonglong2 b0 = *(const ulonglong2*)&Bs[kk][tx * 8];
            ulonglong2 b1 = *(const ulonglong2*)&Bs[kk][tx * 8 + 4];
            float a[8] = {a0.x, a0.y, a0.z, a0.w, a1.x, a1.y, a1.z, a1.w};
            #pragma unroll
            for (int i = 0; i < 8; i++) {
                ull ap = pk(a[i], a[i]);
                acc[i][0] = f2(ap, b0.x, acc[i][0]);
                acc[i][1] = f2(ap, b0.y, acc[i][1]);
                acc[i][2] = f2(ap, b1.x, acc[i][2]);
                acc[i][3] = f2(ap, b1.y, acc[i][3]);
            }
        }
        __syncthreads();
    }
    int n0 = bn * 128 + tx * 8;
    float bb[8];
    #pragma unroll
    for (int j = 0; j < 8; j++) bb[j] = bias[n0 + j];
    #pragma unroll
    for (int i = 0; i < 8; i++) {
        int m = bm * 128 + ty * 8 + i;
        if (m < 3136) {
            float* dst = g_att1 + (size_t)m * 1024 + n0;
            #pragma unroll
            for (int j = 0; j < 4; j++) {
                float2 v = upk(acc[i][j]);
                dst[2 * j + 0] = v.x + bb[2 * j + 0];
                dst[2 * j + 1] = v.y + bb[2 * j + 1];
            }
        }
    }
}

// ================= persistent step kernel ==================================
__global__ void __launch_bounds__(256, 1)
kstep(const float* __restrict__ enc,
      const float* __restrict__ decW, const float* __restrict__ decB,
      const float* __restrict__ fullW, const float* __restrict__ fullB,
      const float* __restrict__ fbW, const float* __restrict__ fbB,
      const float* __restrict__ emb,
      const float* __restrict__ Wih, const float* __restrict__ bih,
      const float* __restrict__ Whh, const float* __restrict__ bhh,
      const float* __restrict__ fcW, const float* __restrict__ fcB,
      const int* __restrict__ caps_in, const int* __restrict__ clen,
      float* __restrict__ out)
{
    __shared__ ull sb8[4096];           // 32KB, reused per phase
    __shared__ int s_sort[16], s_dlen[16];
    float* sbuf = (float*)sb8;
    const int tid = threadIdx.x;
    const int bid = blockIdx.x;
    const int lane = tid & 31;
    const int wrp  = tid >> 5;
    unsigned mygen  = *(volatile unsigned*)&g_gen;
    unsigned mygenA = *(volatile unsigned*)&g_genA;

    // -------- local setup: every block computes the sort itself ----------
    local_sort(clen, s_sort, s_dlen);
    __syncthreads();
    if (bid == 0) {
        if (tid < 16) {
            out[OFF_SORT + tid] = (float)s_sort[tid];
            out[OFF_DLEN + tid] = (float)s_dlen[tid];
        }
        if (tid < 256) {
            for (int j = tid; j < 512; j += 256) {
                int b = j >> 5, l = j & 31;
                out[OFF_CAPS + j] = (float)caps_in[s_sort[b] * 32 + l];
            }
        }
    }

    // -------- phase E: vocab projection for step tp (reads g_hT) ----------
    auto phaseE = [&](int tp, int start, int stride) {
        for (int ch = start; ch < 79; ch += stride) {
            int v0 = ch * 128;
            int vcol = v0 + lane * 4;
            ull acc[4][8];
            #pragma unroll
            for (int c = 0; c < 4; c++)
                #pragma unroll
                for (int j = 0; j < 8; j++) acc[c][j] = 0ull;
            if (vcol < 10000) {
                const float* wp = fcW + (size_t)(wrp * 64) * 10000 + vcol;
                const float* xb = g_hT + (wrp * 64) * 16;
                #pragma unroll 4
                for (int i = 0; i < 64; i++) {
                    float4 w4 = *(const float4*)(wp + (size_t)i * 10000);
                    const ulonglong2* xr = (const ulonglong2*)(xb + i * 16);
                    ulonglong2 x0 = xr[0], x1 = xr[1], x2 = xr[2], x3 = xr[3];
                    ull xv[8] = {x0.x, x0.y, x1.x, x1.y, x2.x, x2.y, x3.x, x3.y};
                    float wf[4] = {w4.x, w4.y, w4.z, w4.w};
                    #pragma unroll
                    for (int c = 0; c < 4; c++) {
                        ull wb = pk(wf[c], wf[c]);
                        #pragma unroll
                        for (int j = 0; j < 8; j++)
                            acc[c][j] = f2(xv[j], wb, acc[c][j]);
                    }
                }
            }
            ull* s = sb8;
            if (wrp < 4) {
                #pragma unroll
                for (int c = 0; c < 4; c++)
                    #pragma unroll
                    for (int j = 0; j < 8; j++)
                        s[(((wrp) * 32 + lane) * 4 + c) * 8 + j] = acc[c][j];
            }
            __syncthreads();
            if (wrp >= 4) {
                int p = wrp - 4;
                #pragma unroll
                for (int c = 0; c < 4; c++)
                    #pragma unroll
                    for (int j = 0; j < 8; j++) {
                        int idx = (((p) * 32 + lane) * 4 + c) * 8 + j;
                        s[idx] = addf2(s[idx], acc[c][j]);
                    }
            }
            __syncthreads();
            #pragma unroll
            for (int q = 0; q < 4; q++) {
                int o = q * 256 + tid;
                int col = o & 127, bp = o >> 7;
                int v = v0 + col;
                if (v < 10000) {
                    int cg = col >> 2, cc = col & 3;
                    ull sm = s[((0 * 32 + cg) * 4 + cc) * 8 + bp];
                    sm = addf2(sm, s[((1 * 32 + cg) * 4 + cc) * 8 + bp]);
                    sm = addf2(sm, s[((2 * 32 + cg) * 4 + cc) * 8 + bp]);
                    sm = addf2(sm, s[((3 * 32 + cg) * 4 + cc) * 8 + bp]);
                    float2 r = upk(sm);
                    float fb = fcB[v];
                    int b0 = 2 * bp, b1 = b0 + 1;
                    out[OFF_PRED + (size_t)(b0 * 31 + tp) * 10000 + v] =
                        (s_dlen[b0] > tp) ? (r.x + fb) : 0.f;
                    out[OFF_PRED + (size_t)(b1 * 31 + tp) * 10000 + v] =
                        (s_dlen[b1] > tp) ? (r.y + fb) : 0.f;
                }
            }
            __syncthreads();
        }
    };

    for (int t = 0; t < 31; t++) {
        if (bid < 64) {
            // ---------- A1: att2 + gate GEMV (2048 virt cols, K=512) ------
            {
                int cg = tid & 7, ks = tid >> 3;
                int c0 = bid * 32;
                int colg = c0 + cg * 4;
                const float* wp = (colg < 1024)
                    ? (decW + (size_t)(ks * 16) * 1024 + colg)
                    : (fbW + (size_t)(ks * 16) * 1024 + (colg - 1024));
                const float* xb = g_xT + (1536 + ks * 16) * 16;
                ull acc[4][8];
                #pragma unroll
                for (int c = 0; c < 4; c++)
                    #pragma unroll
                    for (int j = 0; j < 8; j++) acc[c][j] = 0ull;
                #pragma unroll 4
                for (int i = 0; i < 16; i++) {
                    float4 w4 = *(const float4*)(wp + (size_t)i * 1024);
                    const ulonglong2* xr = (const ulonglong2*)(xb + i * 16);
                    ulonglong2 x0 = xr[0], x1 = xr[1], x2 = xr[2], x3 = xr[3];
                    ull xv[8] = {x0.x, x0.y, x1.x, x1.y, x2.x, x2.y, x3.x, x3.y};
                    float wf[4] = {w4.x, w4.y, w4.z, w4.w};
                    #pragma unroll
                    for (int c = 0; c < 4; c++) {
                        ull wb = pk(wf[c], wf[c]);
                        #pragma unroll
                        for (int j = 0; j < 8; j++)
                            acc[c][j] = f2(xv[j], wb, acc[c][j]);
                    }
                }
                #pragma unroll
                for (int c = 0; c < 4; c++)
                    #pragma unroll
                    for (int j = 0; j < 8; j++) {
                        acc[c][j] = addf2(acc[c][j],
                            __shfl_xor_sync(0xffffffffu, acc[c][j], 8));
                        acc[c][j] = addf2(acc[c][j],
                            __shfl_xor_sync(0xffffffffu, acc[c][j], 16));
                    }
                if (lane < 8) {
                    #pragma unroll
                    for (int c = 0; c < 4; c++)
                        #pragma unroll
                        for (int j = 0; j < 8; j++)
                            sb8[(((wrp) * 8 + lane) * 4 + c) * 8 + j] = acc[c][j];
                }
                __syncthreads();
                {
                    int col = tid >> 3, bp = tid & 7;
                    int cg2 = col >> 2, cc = col & 3;
                    ull sm = sb8[((0 * 8 + cg2) * 4 + cc) * 8 + bp];
                    #pragma unroll
                    for (int w = 1; w < 8; w++)
                        sm = addf2(sm, sb8[((w * 8 + cg2) * 4 + cc) * 8 + bp]);
                    float2 r = upk(sm);
                    int ocol = c0 + col;
                    int b0 = 2 * bp, b1 = b0 + 1;
                    if (ocol < 1024) {
                        float db = decB[ocol];
                        g_att2[b0 * 1024 + ocol] = r.x + db;
                        g_att2[b1 * 1024 + ocol] = r.y + db;
                    } else {
                        int oc = ocol - 1024;
                        float fb = fbB[oc];
                        g_gate[b0 * 1024 + oc] = sigmf(r.x + fb);
                        g_gate[b1 * 1024 + oc] = sigmf(r.y + fb);
                    }
                }
            }
            // ---------- partial barrier over blocks 0..63 -----------------
            bar_sync(&g_cntA, &g_genA, 64, mygenA);

            if (bid < 16) {
                // ---------- A2: fused scores+softmax+alphas+awe (1 batch) -
                float* s_att2 = sbuf;            // 1024
                float* s_fw   = sbuf + 1024;     // 1024
                float* s_al   = sbuf + 2048;     // 200
                float* s_rd   = sbuf + 2304;     // 8
                float* s_sc   = sbuf + 2336;     // 1
                int b = bid;
                for (int j = tid; j < 1024; j += 256) {
                    s_att2[j] = g_att2[b * 1024 + j];
                    s_fw[j]   = fullW[j];
                }
                __syncthreads();
                float fb0 = fullB[0];
                #pragma unroll 2
                for (int p = wrp; p < 196; p += 8) {
                    const float* row = g_att1 + (size_t)(b * 196 + p) * 1024;
                    float acc = 0.f;
                    #pragma unroll
                    for (int eq = 0; eq < 8; eq++) {
                        int e = eq * 128 + lane * 4;
                        float4 x  = *(const float4*)(row + e);
                        float4 a2 = *(const float4*)&s_att2[e];
                        float4 w  = *(const float4*)&s_fw[e];
                        acc += fmaxf(x.x + a2.x, 0.f) * w.x;
                        acc += fmaxf(x.y + a2.y, 0.f) * w.y;
                        acc += fmaxf(x.z + a2.z, 0.f) * w.z;
                        acc += fmaxf(x.w + a2.w, 0.f) * w.w;
                    }
                    #pragma unroll
                    for (int o = 16; o > 0; o >>= 1)
                        acc += __shfl_xor_sync(0xffffffffu, acc, o);
                    if (lane == 0) s_al[p] = acc + fb0;
                }
                __syncthreads();
                float sc = (tid < 196) ? s_al[tid] : -1e30f;
                float v = sc;
                #pragma unroll
                for (int o = 16; o > 0; o >>= 1)
                    v = fmaxf(v, __shfl_xor_sync(0xffffffffu, v, o));
                if (lane == 0) s_rd[wrp] = v;
                __syncthreads();
                if (tid == 0) {
                    float m = s_rd[0];
                    #pragma unroll
                    for (int i = 1; i < 8; i++) m = fmaxf(m, s_rd[i]);
                    s_sc[0] = m;
                }
                __syncthreads();
                float ex = (tid < 196) ? expf(sc - s_sc[0]) : 0.f;
                v = ex;
                #pragma unroll
                for (int o = 16; o > 0; o >>= 1)
                    v += __shfl_xor_sync(0xffffffffu, v, o);
                if (lane == 0) s_rd[wrp] = v;
                __syncthreads();
                if (tid == 0) {
                    float s = 0.f;
                    #pragma unroll
                    for (int i = 0; i < 8; i++) s += s_rd[i];
                    s_sc[0] = 1.0f / s;
                }
                __syncthreads();
                float alpha = ex * s_sc[0];
                bool act = s_dlen[b] > t;
                if (tid < 196) {
                    s_al[tid] = alpha;
                    out[OFF_ALPH + (size_t)(b * 31 + t) * 196 + tid] = act ? alpha : 0.f;
                }
                __syncthreads();
                int e4 = tid * 4;
                const float* ep = enc + ((size_t)s_sort[b] * 196) * 1024 + e4;
                float ax = 0.f, ay = 0.f, az = 0.f, aw = 0.f;
                #pragma unroll 16
                for (int p = 0; p < 196; p++) {
                    float al = s_al[p];
                    float4 ev = *(const float4*)(ep + (size_t)p * 1024);
                    ax += al * ev.x; ay += al * ev.y;
                    az += al * ev.z; aw += al * ev.w;
                }
                const float* gr = g_gate + b * 1024 + e4;
                g_xT[(512 + e4 + 0) * 16 + b] = ax + gr[0];
                g_xT[(512 + e4 + 1) * 16 + b] = ay + gr[1];
                g_xT[(512 + e4 + 2) * 16 + b] = az + gr[2];
                g_xT[(512 + e4 + 3) * 16 + b] = aw + gr[3];
            } else {
                // ---------- emb fill on blocks 16..63 ---------------------
                int j = (bid - 16) * 256 + tid;
                if (j < 8192) {
                    int b = j >> 9, k = j & 511;
                    int tok = caps_in[s_sort[b] * 32 + t];
                    g_xT[k * 16 + b] = emb[(size_t)tok * 512 + k];
                }
            }
        } else {
            // ---------- group B: vocab projection for t-1 -----------------
            if (t > 0) phaseE(t - 1, bid - 64, 84);
        }
        bar_sync(&g_cnt, &g_gen, NBLK, mygen);

        // ============ fused LSTM gates GEMM + elementwise =================
        if (bid < 128) {
            int d0 = bid * 4;
            int cg = tid & 3, ks = tid >> 2;
            int col = cg * 512 + d0;
            const float* wp = (ks < 48)
                ? (Wih + (size_t)(ks * 32) * 2048 + col)
                : (Whh + (size_t)((ks - 48) * 32) * 2048 + col);
            const float* xb = g_xT + (ks * 32) * 16;
            ull acc[4][8];
            #pragma unroll
            for (int c = 0; c < 4; c++)
                #pragma unroll
                for (int j = 0; j < 8; j++) acc[c][j] = 0ull;
            #pragma unroll 4
            for (int i = 0; i < 32; i++) {
                float4 w4 = *(const float4*)(wp + (size_t)i * 2048);
                const ulonglong2* xr = (const ulonglong2*)(xb + i * 16);
                ulonglong2 x0 = xr[0], x1 = xr[1], x2 = xr[2], x3 = xr[3];
                ull xv[8] = {x0.x, x0.y, x1.x, x1.y, x2.x, x2.y, x3.x, x3.y};
                float wf[4] = {w4.x, w4.y, w4.z, w4.w};
                #pragma unroll
                for (int c = 0; c < 4; c++) {
                    ull wb = pk(wf[c], wf[c]);
                    #pragma unroll
                    for (int j = 0; j < 8; j++)
                        acc[c][j] = f2(xv[j], wb, acc[c][j]);
                }
            }
            #pragma unroll
            for (int c = 0; c < 4; c++)
                #pragma unroll
                for (int j = 0; j < 8; j++) {
                    acc[c][j] = addf2(acc[c][j],
                        __shfl_xor_sync(0xffffffffu, acc[c][j], 4));
                    acc[c][j] = addf2(acc[c][j],
                        __shfl_xor_sync(0xffffffffu, acc[c][j], 8));
                    acc[c][j] = addf2(acc[c][j],
                        __shfl_xor_sync(0xffffffffu, acc[c][j], 16));
                }
            if (lane < 4) {
                #pragma unroll
                for (int c = 0; c < 4; c++)
                    #pragma unroll
                    for (int j = 0; j < 8; j++)
                        sb8[(((wrp) * 4 + lane) * 4 + c) * 8 + j] = acc[c][j];
            }
            float* s_gt = (float*)(sb8 + 1024);   // [16][16]
            __syncthreads();
            if (tid < 128) {
                int c = tid >> 3, bp = tid & 7;
                int g = c >> 2, dd = c & 3;
                ull sm = sb8[((0 * 4 + g) * 4 + dd) * 8 + bp];
                #pragma unroll
                for (int w = 1; w < 8; w++)
                    sm = addf2(sm, sb8[((w * 4 + g) * 4 + dd) * 8 + bp]);
                float2 r = upk(sm);
                int col2 = g * 512 + d0 + dd;
                float bb = bih[col2] + bhh[col2];
                s_gt[c * 16 + 2 * bp + 0] = r.x + bb;
                s_gt[c * 16 + 2 * bp + 1] = r.y + bb;
            }
            __syncthreads();
            if (tid < 64) {
                int dd2 = tid >> 4, b = tid & 15;
                int d = d0 + dd2;
                float gi = s_gt[(0 + dd2) * 16 + b];
                float gf = s_gt[(4 + dd2) * 16 + b];
                float gc = s_gt[(8 + dd2) * 16 + b];
                float go = s_gt[(12 + dd2) * 16 + b];
                int gid = b * 512 + d;
                float cold = g_c[gid];
                float cnew = sigmf(gf) * cold + sigmf(gi) * tanhf(gc);
                float hnew = sigmf(go) * tanhf(cnew);
                bool act = s_dlen[b] > t;
                float h2 = act ? hnew : g_h[gid];
                float c2v = act ? cnew : cold;
                g_h[gid] = h2;
                g_c[gid] = c2v;
                g_hT[d * 16 + b] = hnew;
                g_xT[(1536 + d) * 16 + b] = h2;
            }
        }
        bar_sync(&g_cnt, &g_gen, NBLK, mygen);
    }

    // final vocab projection for t = 30 on all blocks
    phaseE(30, bid, NBLK);
}

// ================= launcher ==============================================
extern "C" void kernel_launch(void* const* d_in, const int* in_sizes, int n_in,
                              void* d_out, int out_size) {
    const float* enc    = (const float*)d_in[0];
    const float* encW   = (const float*)d_in[1];
    const float* encB   = (const float*)d_in[2];
    const float* decW   = (const float*)d_in[3];
    const float* decB   = (const float*)d_in[4];
    const float* fullW  = (const float*)d_in[5];
    const float* fullB  = (const float*)d_in[6];
    const float* emb    = (const float*)d_in[7];
    const float* Wih    = (const float*)d_in[8];
    const float* bih    = (const float*)d_in[9];
    const float* Whh    = (const float*)d_in[10];
    const float* bhh    = (const float*)d_in[11];
    const float* ihW    = (const float*)d_in[12];
    const float* ihB    = (const float*)d_in[13];
    const float* icW    = (const float*)d_in[14];
    const float* icB    = (const float*)d_in[15];
    const float* fbW    = (const float*)d_in[16];
    const float* fbB    = (const float*)d_in[17];
    const float* fcW    = (const float*)d_in[18];
    const float* fcB    = (const float*)d_in[19];
    const int*   capsin = (const int*)d_in[20];
    const int*   clen   = (const int*)d_in[21];
    float* out = (float*)d_out;

    katt1<<<dim3(8, 26), 256>>>(enc, encW, encB, ihW, ihB, icW, icB, clen);
    kstep<<<NBLK, 256>>>(enc, decW, decB, fullW, fullB, fbW, fbB, emb,
                         Wih, bih, Whh, bhh, fcW, fcB, capsin, clen, out);
}

// round 12
// speedup vs baseline: 1.2763x; 1.1971x over previous
#include <cuda_runtime.h>
#include <cstdint>
#include <cstddef>

typedef unsigned long long ull;

// ---------------- output layout (float32 concat of reference tuple) -------
#define OFF_PRED 0
#define OFF_CAPS 4960000
#define OFF_DLEN 4960512
#define OFF_ALPH 4960528
#define OFF_SORT 5057744

#define NBLK 148

// ---------------- device scratch (static globals: no allocs) --------------
__device__ float g_att1[3136 * 1024];     // 12.8 MB
__device__ float g_mean[16 * 1024];
__device__ float g_h[16 * 512], g_c[16 * 512];
__device__ float g_hT[512 * 16];          // h_new transposed [d][b]
__device__ float g_xT[2048 * 16];         // X transposed [k][b]: emb|awe|h
__device__ float g_att2[16 * 1024], g_gate[16 * 1024];
__device__ unsigned g_cnt = 0, g_gen = 0;       // full barrier
__device__ unsigned g_cntA = 0, g_genA = 0;     // partial (64-block) barrier

// ---------------- helpers ----------------
__device__ __forceinline__ ull pk(float x, float y) {
    ull u; asm("mov.b64 %0,{%1,%2};" : "=l"(u) : "f"(x), "f"(y)); return u;
}
__device__ __forceinline__ float2 upk(ull u) {
    float2 v; asm("mov.b64 {%0,%1},%2;" : "=f"(v.x), "=f"(v.y) : "l"(u)); return v;
}
__device__ __forceinline__ ull f2(ull a, ull b, ull c) {
    ull d; asm("fma.rn.f32x2 %0,%1,%2,%3;" : "=l"(d) : "l"(a), "l"(b), "l"(c)); return d;
}
__device__ __forceinline__ ull addf2(ull a, ull b) {
    ull d; asm("add.rn.f32x2 %0,%1,%2;" : "=l"(d) : "l"(a), "l"(b)); return d;
}
__device__ __forceinline__ float sigmf(float x) { return 1.f / (1.f + expf(-x)); }

__device__ __forceinline__ void bar_sync(unsigned* cnt, unsigned* gen,
                                         unsigned count, unsigned& mygen) {
    __syncthreads();
    if (threadIdx.x == 0) {
        __threadfence();
        if (atomicAdd(cnt, 1u) == count - 1) {
            *cnt = 0;
            __threadfence();
            *(volatile unsigned*)gen = mygen + 1;
        } else {
            while (*(volatile unsigned*)gen == mygen) { }
            __threadfence();
        }
    }
    mygen++;
    __syncthreads();
}

// local stable-descending sort of lengths; fills s_sort/s_dlen in smem.
__device__ __forceinline__ void local_sort(const int* __restrict__ clen,
                                           int* s_sort, int* s_dlen) {
    int tid = threadIdx.x;
    if (tid < 16) {
        int li = clen[tid];
        int rank = 0;
        #pragma unroll
        for (int j = 0; j < 16; j++) {
            int lj = clen[j];
            rank += (lj > li) || (lj == li && j < tid);
        }
        s_sort[rank] = tid;
        s_dlen[rank] = li - 1;
    }
}

// ================= att1 GEMM (pure, as in R5) ==============================
__global__ void __launch_bounds__(256, 1)
katt1(const float* __restrict__ enc, const float* __restrict__ W,
      const float* __restrict__ bias, const int* __restrict__ clen) {
    __shared__ float As[32][132];
    __shared__ float Bs[32][128];
    __shared__ int s_sort[16], s_dlen[16];
    int tid = threadIdx.x;
    int bm = blockIdx.y, bn = blockIdx.x;

    local_sort(clen, s_sort, s_dlen);
    __syncthreads();

    int kq = tid & 7, ml = tid >> 3;
    const float* arow[4];
    #pragma unroll
    for (int ps = 0; ps < 4; ps++) {
        int m = bm * 128 + ml + ps * 32;
        int mc = m < 3135 ? m : 3135;
        int b = mc / 196, p = mc - b * 196;
        arow[ps] = enc + ((size_t)s_sort[b] * 196 + p) * 1024 + kq * 4;
    }
    int nb = tid & 31, kb = tid >> 5;
    const float* bptr = W + (size_t)kb * 1024 + bn * 128 + nb * 4;

    ull acc[8][4];
    #pragma unroll
    for (int i = 0; i < 8; i++)
        #pragma unroll
        for (int j = 0; j < 4; j++) acc[i][j] = 0ull;

    int tx = tid & 15, ty = tid >> 4;

    float4 ra[4], rb[4];
    #pragma unroll
    for (int ps = 0; ps < 4; ps++) ra[ps] = *(const float4*)(arow[ps]);
    #pragma unroll
    for (int ps = 0; ps < 4; ps++) rb[ps] = *(const float4*)(bptr + (size_t)(ps * 8) * 1024);

    for (int kt = 0; kt < 1024; kt += 32) {
        #pragma unroll
        for (int ps = 0; ps < 4; ps++) {
            int mm = ml + ps * 32;
            As[kq * 4 + 0][mm] = ra[ps].x;
            As[kq * 4 + 1][mm] = ra[ps].y;
            As[kq * 4 + 2][mm] = ra[ps].z;
            As[kq * 4 + 3][mm] = ra[ps].w;
        }
        #pragma unroll
        for (int ps = 0; ps < 4; ps++)
            *(float4*)&Bs[kb + ps * 8][nb * 4] = rb[ps];
        __syncthreads();
        if (kt + 32 < 1024) {
            #pragma unroll
            for (int ps = 0; ps < 4; ps++)
                ra[ps] = *(const float4*)(arow[ps] + kt + 32);
            #pragma unroll
            for (int ps = 0; ps < 4; ps++)
                rb[ps] = *(const float4*)(bptr + (size_t)(kt + 32 + ps * 8) * 1024);
        }
        #pragma unroll 8
        for (int kk = 0; kk < 32; kk++) {
            float4 a0 = *(const float4*)&As[kk][ty * 8];
            float4 a1 = *(const float4*)&As[kk][ty * 8 + 4];
            ulonglong2 b0 = *(const ulonglong2*)&Bs[kk][tx * 8];
            ulonglong2 b1 = *(const ulonglong2*)&Bs[kk][tx * 8 + 4];
            float a[8] = {a0.x, a0.y, a0.z, a0.w, a1.x, a1.y, a1.z, a1.w};
            #pragma unroll
            for (int i = 0; i < 8; i++) {
                ull ap = pk(a[i], a[i]);
                acc[i][0] = f2(ap, b0.x, acc[i][0]);
                acc[i][1] = f2(ap, b0.y, acc[i][1]);
                acc[i][2] = f2(ap, b1.x, acc[i][2]);
                acc[i][3] = f2(ap, b1.y, acc[i][3]);
            }
        }
        __syncthreads();
    }
    int n0 = bn * 128 + tx * 8;
    float bb[8];
    #pragma unroll
    for (int j = 0; j < 8; j++) bb[j] = bias[n0 + j];
    #pragma unroll
    for (int i = 0; i < 8; i++) {
        int m = bm * 128 + ty * 8 + i;
        if (m < 3136) {
            float* dst = g_att1 + (size_t)m * 1024 + n0;
            #pragma unroll
            for (int j = 0; j < 4; j++) {
                float2 v = upk(acc[i][j]);
                dst[2 * j + 0] = v.x + bb[2 * j + 0];
                dst[2 * j + 1] = v.y + bb[2 * j + 1];
            }
        }
    }
}

// ================= persistent step kernel ==================================
__global__ void __launch_bounds__(256, 1)
kstep(const float* __restrict__ enc,
      const float* __restrict__ decW, const float* __restrict__ decB,
      const float* __restrict__ fullW, const float* __restrict__ fullB,
      const float* __restrict__ fbW, const float* __restrict__ fbB,
      const float* __restrict__ emb,
      const float* __restrict__ Wih, const float* __restrict__ bih,
      const float* __restrict__ Whh, const float* __restrict__ bhh,
      const float* __restrict__ fcW, const float* __restrict__ fcB,
      const float* __restrict__ ihW, const float* __restrict__ ihB,
      const float* __restrict__ icW, const float* __restrict__ icB,
      const int* __restrict__ caps_in, const int* __restrict__ clen,
      float* __restrict__ out)
{
    __shared__ ull sb8[4096];           // 32KB, reused per phase
    __shared__ int s_sort[16], s_dlen[16];
    float* sbuf = (float*)sb8;
    const int tid = threadIdx.x;
    const int bid = blockIdx.x;
    const int lane = tid & 31;
    const int wrp  = tid >> 5;
    unsigned mygen  = *(volatile unsigned*)&g_gen;
    unsigned mygenA = *(volatile unsigned*)&g_genA;

    // -------- local setup: every block computes the sort itself ----------
    local_sort(clen, s_sort, s_dlen);
    __syncthreads();
    if (bid == 0) {
        if (tid < 16) {
            out[OFF_SORT + tid] = (float)s_sort[tid];
            out[OFF_DLEN + tid] = (float)s_dlen[tid];
        }
        for (int j = tid; j < 512; j += 256) {
            int b = j >> 5, l = j & 31;
            out[OFF_CAPS + j] = (float)caps_in[s_sort[b] * 32 + l];
        }
    }

    // ============ Prologue S1: mean over P (128 blocks) ===================
    if (bid < 128) {
        // outputs o = bid*128 + i, i = tid>>1; half = tid&1 sums 98 p's
        int i = tid >> 1, half = tid & 1;
        int o = bid * 128 + i;
        int b = o >> 10, e = o & 1023;
        const float* p0 = enc + ((size_t)s_sort[b] * 196 + half * 98) * 1024 + e;
        float s = 0.f;
        #pragma unroll 14
        for (int p = 0; p < 98; p++) s += p0[(size_t)p * 1024];
        sbuf[half * 128 + i] = s;
        __syncthreads();
        if (tid < 128)
            g_mean[bid * 128 + tid] =
                (sbuf[tid] + sbuf[128 + tid]) * (1.0f / 196.0f);
    }
    bar_sync(&g_cnt, &g_gen, NBLK, mygen);

    // ============ Prologue S2: h0/c0 GEMV (128 blocks) ====================
    if (bid < 128) {
        // bid -> (b, which, dchunk): b = bid>>3, which = (bid>>2)&1, dchunk = bid&3
        int b = bid >> 3, which = (bid >> 2) & 1, dchunk = bid & 3;
        int cg = tid & 31, ks = tid >> 5;          // 32 col-groups, 8 k-slices
        int d = dchunk * 128 + cg * 4;
        const float* W = which ? icW : ihW;
        const float* wp = W + (size_t)(ks * 128) * 512 + d;
        const float* xp = g_mean + b * 1024 + ks * 128;
        float acc0 = 0.f, acc1 = 0.f, acc2 = 0.f, acc3 = 0.f;
        #pragma unroll 16
        for (int i = 0; i < 128; i++) {
            float4 w4 = *(const float4*)(wp + (size_t)i * 512);
            float x = xp[i];
            acc0 += x * w4.x; acc1 += x * w4.y;
            acc2 += x * w4.z; acc3 += x * w4.w;
        }
        float* sr = sbuf;                          // [8][128]
        sr[ks * 128 + cg * 4 + 0] = acc0;
        sr[ks * 128 + cg * 4 + 1] = acc1;
        sr[ks * 128 + cg * 4 + 2] = acc2;
        sr[ks * 128 + cg * 4 + 3] = acc3;
        __syncthreads();
        if (tid < 128) {
            float s = 0.f;
            #pragma unroll
            for (int k = 0; k < 8; k++) s += sr[k * 128 + tid];
            int dd = dchunk * 128 + tid;
            float val = s + (which ? icB[dd] : ihB[dd]);
            if (which) g_c[b * 512 + dd] = val;
            else { g_h[b * 512 + dd] = val; g_xT[(1536 + dd) * 16 + b] = val; }
        }
    }
    bar_sync(&g_cnt, &g_gen, NBLK, mygen);

    // -------- phase E: vocab projection for step tp (reads g_hT) ----------
    auto phaseE = [&](int tp, int start, int stride) {
        for (int ch = start; ch < 79; ch += stride) {
            int v0 = ch * 128;
            int vcol = v0 + lane * 4;
            ull acc[4][8];
            #pragma unroll
            for (int c = 0; c < 4; c++)
                #pragma unroll
                for (int j = 0; j < 8; j++) acc[c][j] = 0ull;
            if (vcol < 10000) {
                const float* wp = fcW + (size_t)(wrp * 64) * 10000 + vcol;
                const float* xb = g_hT + (wrp * 64) * 16;
                #pragma unroll 4
                for (int i = 0; i < 64; i++) {
                    float4 w4 = *(const float4*)(wp + (size_t)i * 10000);
                    const ulonglong2* xr = (const ulonglong2*)(xb + i * 16);
                    ulonglong2 x0 = xr[0], x1 = xr[1], x2 = xr[2], x3 = xr[3];
                    ull xv[8] = {x0.x, x0.y, x1.x, x1.y, x2.x, x2.y, x3.x, x3.y};
                    float wf[4] = {w4.x, w4.y, w4.z, w4.w};
                    #pragma unroll
                    for (int c = 0; c < 4; c++) {
                        ull wb = pk(wf[c], wf[c]);
                        #pragma unroll
                        for (int j = 0; j < 8; j++)
                            acc[c][j] = f2(xv[j], wb, acc[c][j]);
                    }
                }
            }
            ull* s = sb8;
            if (wrp < 4) {
                #pragma unroll
                for (int c = 0; c < 4; c++)
                    #pragma unroll
                    for (int j = 0; j < 8; j++)
                        s[(((wrp) * 32 + lane) * 4 + c) * 8 + j] = acc[c][j];
            }
            __syncthreads();
            if (wrp >= 4) {
                int p = wrp - 4;
                #pragma unroll
                for (int c = 0; c < 4; c++)
                    #pragma unroll
                    for (int j = 0; j < 8; j++) {
                        int idx = (((p) * 32 + lane) * 4 + c) * 8 + j;
                        s[idx] = addf2(s[idx], acc[c][j]);
                    }
            }
            __syncthreads();
            #pragma unroll
            for (int q = 0; q < 4; q++) {
                int o = q * 256 + tid;
                int col = o & 127, bp = o >> 7;
                int v = v0 + col;
                if (v < 10000) {
                    int cg = col >> 2, cc = col & 3;
                    ull sm = s[((0 * 32 + cg) * 4 + cc) * 8 + bp];
                    sm = addf2(sm, s[((1 * 32 + cg) * 4 + cc) * 8 + bp]);
                    sm = addf2(sm, s[((2 * 32 + cg) * 4 + cc) * 8 + bp]);
                    sm = addf2(sm, s[((3 * 32 + cg) * 4 + cc) * 8 + bp]);
                    float2 r = upk(sm);
                    float fb = fcB[v];
                    int b0 = 2 * bp, b1 = b0 + 1;
                    out[OFF_PRED + (size_t)(b0 * 31 + tp) * 10000 + v] =
                        (s_dlen[b0] > tp) ? (r.x + fb) : 0.f;
                    out[OFF_PRED + (size_t)(b1 * 31 + tp) * 10000 + v] =
                        (s_dlen[b1] > tp) ? (r.y + fb) : 0.f;
                }
            }
            __syncthreads();
        }
    };

    for (int t = 0; t < 31; t++) {
        if (bid < 64) {
            // ---------- A1: att2 + gate GEMV (2048 virt cols, K=512) ------
            {
                int cg = tid & 7, ks = tid >> 3;
                int c0 = bid * 32;
                int colg = c0 + cg * 4;
                const float* wp = (colg < 1024)
                    ? (decW + (size_t)(ks * 16) * 1024 + colg)
                    : (fbW + (size_t)(ks * 16) * 1024 + (colg - 1024));
                const float* xb = g_xT + (1536 + ks * 16) * 16;
                ull acc[4][8];
                #pragma unroll
                for (int c = 0; c < 4; c++)
                    #pragma unroll
                    for (int j = 0; j < 8; j++) acc[c][j] = 0ull;
                #pragma unroll 4
                for (int i = 0; i < 16; i++) {
                    float4 w4 = *(const float4*)(wp + (size_t)i * 1024);
                    const ulonglong2* xr = (const ulonglong2*)(xb + i * 16);
                    ulonglong2 x0 = xr[0], x1 = xr[1], x2 = xr[2], x3 = xr[3];
                    ull xv[8] = {x0.x, x0.y, x1.x, x1.y, x2.x, x2.y, x3.x, x3.y};
                    float wf[4] = {w4.x, w4.y, w4.z, w4.w};
                    #pragma unroll
                    for (int c = 0; c < 4; c++) {
                        ull wb = pk(wf[c], wf[c]);
                        #pragma unroll
                        for (int j = 0; j < 8; j++)
                            acc[c][j] = f2(xv[j], wb, acc[c][j]);
                    }
                }
                #pragma unroll
                for (int c = 0; c < 4; c++)
                    #pragma unroll
                    for (int j = 0; j < 8; j++) {
                        acc[c][j] = addf2(acc[c][j],
                            __shfl_xor_sync(0xffffffffu, acc[c][j], 8));
                        acc[c][j] = addf2(acc[c][j],
                            __shfl_xor_sync(0xffffffffu, acc[c][j], 16));
                    }
                if (lane < 8) {
                    #pragma unroll
                    for (int c = 0; c < 4; c++)
                        #pragma unroll
                        for (int j = 0; j < 8; j++)
                            sb8[(((wrp) * 8 + lane) * 4 + c) * 8 + j] = acc[c][j];
                }
                __syncthreads();
                {
                    int col = tid >> 3, bp = tid & 7;
                    int cg2 = col >> 2, cc = col & 3;
                    ull sm = sb8[((0 * 8 + cg2) * 4 + cc) * 8 + bp];
                    #pragma unroll
                    for (int w = 1; w < 8; w++)
                        sm = addf2(sm, sb8[((w * 8 + cg2) * 4 + cc) * 8 + bp]);
                    float2 r = upk(sm);
                    int ocol = c0 + col;
                    int b0 = 2 * bp, b1 = b0 + 1;
                    if (ocol < 1024) {
                        float db = decB[ocol];
                        g_att2[b0 * 1024 + ocol] = r.x + db;
                        g_att2[b1 * 1024 + ocol] = r.y + db;
                    } else {
                        int oc = ocol - 1024;
                        float fb = fbB[oc];
                        g_gate[b0 * 1024 + oc] = sigmf(r.x + fb);
                        g_gate[b1 * 1024 + oc] = sigmf(r.y + fb);
                    }
                }
            }
            // ---------- partial barrier over blocks 0..63 -----------------
            bar_sync(&g_cntA, &g_genA, 64, mygenA);

            if (bid < 16) {
                // ---------- A2: fused scores+softmax+alphas+awe (1 batch) -
                float* s_att2 = sbuf;            // 1024
                float* s_fw   = sbuf + 1024;     // 1024
                float* s_al   = sbuf + 2048;     // 200
                float* s_rd   = sbuf + 2304;     // 8
                float* s_sc   = sbuf + 2336;     // 1
                int b = bid;
                for (int j = tid; j < 1024; j += 256) {
                    s_att2[j] = g_att2[b * 1024 + j];
                    s_fw[j]   = fullW[j];
                }
                __syncthreads();
                float fb0 = fullB[0];
                #pragma unroll 2
                for (int p = wrp; p < 196; p += 8) {
                    const float* row = g_att1 + (size_t)(b * 196 + p) * 1024;
                    float acc = 0.f;
                    #pragma unroll
                    for (int eq = 0; eq < 8; eq++) {
                        int e = eq * 128 + lane * 4;
                        float4 x  = *(const float4*)(row + e);
                        float4 a2 = *(const float4*)&s_att2[e];
                        float4 w  = *(const float4*)&s_fw[e];
                        acc += fmaxf(x.x + a2.x, 0.f) * w.x;
                        acc += fmaxf(x.y + a2.y, 0.f) * w.y;
                        acc += fmaxf(x.z + a2.z, 0.f) * w.z;
                        acc += fmaxf(x.w + a2.w, 0.f) * w.w;
                    }
                    #pragma unroll
                    for (int o = 16; o > 0; o >>= 1)
                        acc += __shfl_xor_sync(0xffffffffu, acc, o);
                    if (lane == 0) s_al[p] = acc + fb0;
                }
                __syncthreads();
                float sc = (tid < 196) ? s_al[tid] : -1e30f;
                float v = sc;
                #pragma unroll
                for (int o = 16; o > 0; o >>= 1)
                    v = fmaxf(v, __shfl_xor_sync(0xffffffffu, v, o));
                if (lane == 0) s_rd[wrp] = v;
                __syncthreads();
                if (tid == 0) {
                    float m = s_rd[0];
                    #pragma unroll
                    for (int i = 1; i < 8; i++) m = fmaxf(m, s_rd[i]);
                    s_sc[0] = m;
                }
                __syncthreads();
                float ex = (tid < 196) ? expf(sc - s_sc[0]) : 0.f;
                v = ex;
                #pragma unroll
                for (int o = 16; o > 0; o >>= 1)
                    v += __shfl_xor_sync(0xffffffffu, v, o);
                if (lane == 0) s_rd[wrp] = v;
                __syncthreads();
                if (tid == 0) {
                    float s = 0.f;
                    #pragma unroll
                    for (int i = 0; i < 8; i++) s += s_rd[i];
                    s_sc[0] = 1.0f / s;
                }
                __syncthreads();
                float alpha = ex * s_sc[0];
                bool act = s_dlen[b] > t;
                if (tid < 196) {
                    s_al[tid] = alpha;
                    out[OFF_ALPH + (size_t)(b * 31 + t) * 196 + tid] = act ? alpha : 0.f;
                }
                __syncthreads();
                int e4 = tid * 4;
                const float* ep = enc + ((size_t)s_sort[b] * 196) * 1024 + e4;
                float ax = 0.f, ay = 0.f, az = 0.f, aw = 0.f;
                #pragma unroll 16
                for (int p = 0; p < 196; p++) {
                    float al = s_al[p];
                    float4 ev = *(const float4*)(ep + (size_t)p * 1024);
                    ax += al * ev.x; ay += al * ev.y;
                    az += al * ev.z; aw += al * ev.w;
                }
                const float* gr = g_gate + b * 1024 + e4;
                g_xT[(512 + e4 + 0) * 16 + b] = ax + gr[0];
                g_xT[(512 + e4 + 1) * 16 + b] = ay + gr[1];
                g_xT[(512 + e4 + 2) * 16 + b] = az + gr[2];
                g_xT[(512 + e4 + 3) * 16 + b] = aw + gr[3];
            } else {
                // ---------- emb fill on blocks 16..63 ---------------------
                int j = (bid - 16) * 256 + tid;
                if (j < 8192) {
                    int b = j >> 9, k = j & 511;
                    int tok = caps_in[s_sort[b] * 32 + t];
                    g_xT[k * 16 + b] = emb[(size_t)tok * 512 + k];
                }
            }
        } else {
            // ---------- group B: vocab projection for t-1 -----------------
            if (t > 0) phaseE(t - 1, bid - 64, 84);
        }
        bar_sync(&g_cnt, &g_gen, NBLK, mygen);

        // ============ fused LSTM gates GEMM + elementwise =================
        if (bid < 128) {
            int d0 = bid * 4;
            int cg = tid & 3, ks = tid >> 2;
            int col = cg * 512 + d0;
            const float* wp = (ks < 48)
                ? (Wih + (size_t)(ks * 32) * 2048 + col)
                : (Whh + (size_t)((ks - 48) * 32) * 2048 + col);
            const float* xb = g_xT + (ks * 32) * 16;
            ull acc[4][8];
            #pragma unroll
            for (int c = 0; c < 4; c++)
                #pragma unroll
                for (int j = 0; j < 8; j++) acc[c][j] = 0ull;
            #pragma unroll 4
            for (int i = 0; i < 32; i++) {
                float4 w4 = *(const float4*)(wp + (size_t)i * 2048);
                const ulonglong2* xr = (const ulonglong2*)(xb + i * 16);
                ulonglong2 x0 = xr[0], x1 = xr[1], x2 = xr[2], x3 = xr[3];
                ull xv[8] = {x0.x, x0.y, x1.x, x1.y, x2.x, x2.y, x3.x, x3.y};
                float wf[4] = {w4.x, w4.y, w4.z, w4.w};
                #pragma unroll
                for (int c = 0; c < 4; c++) {
                    ull wb = pk(wf[c], wf[c]);
                    #pragma unroll
                    for (int j = 0; j < 8; j++)
                        acc[c][j] = f2(xv[j], wb, acc[c][j]);
                }
            }
            #pragma unroll
            for (int c = 0; c < 4; c++)
                #pragma unroll
                for (int j = 0; j < 8; j++) {
                    acc[c][j] = addf2(acc[c][j],
                        __shfl_xor_sync(0xffffffffu, acc[c][j], 4));
                    acc[c][j] = addf2(acc[c][j],
                        __shfl_xor_sync(0xffffffffu, acc[c][j], 8));
                    acc[c][j] = addf2(acc[c][j],
                        __shfl_xor_sync(0xffffffffu, acc[c][j], 16));
                }
            if (lane < 4) {
                #pragma unroll
                for (int c = 0; c < 4; c++)
                    #pragma unroll
                    for (int j = 0; j < 8; j++)
                        sb8[(((wrp) * 4 + lane) * 4 + c) * 8 + j] = acc[c][j];
            }
            float* s_gt = (float*)(sb8 + 1024);   // [16][16]
            __syncthreads();
            if (tid < 128) {
                int c = tid >> 3, bp = tid & 7;
                int g = c >> 2, dd = c & 3;
                ull sm = sb8[((0 * 4 + g) * 4 + dd) * 8 + bp];
                #pragma unroll
                for (int w = 1; w < 8; w++)
                    sm = addf2(sm, sb8[((w * 4 + g) * 4 + dd) * 8 + bp]);
                float2 r = upk(sm);
                int col2 = g * 512 + d0 + dd;
                float bb = bih[col2] + bhh[col2];
                s_gt[c * 16 + 2 * bp + 0] = r.x + bb;
                s_gt[c * 16 + 2 * bp + 1] = r.y + bb;
            }
            __syncthreads();
            if (tid < 64) {
                int dd2 = tid >> 4, b = tid & 15;
                int d = d0 + dd2;
                float gi = s_gt[(0 + dd2) * 16 + b];
                float gf = s_gt[(4 + dd2) * 16 + b];
                float gc = s_gt[(8 + dd2) * 16 + b];
                float go = s_gt[(12 + dd2) * 16 + b];
                int gid = b * 512 + d;
                float cold = g_c[gid];
                float cnew = sigmf(gf) * cold + sigmf(gi) * tanhf(gc);
                float hnew = sigmf(go) * tanhf(cnew);
                bool act = s_dlen[b] > t;
                float h2 = act ? hnew : g_h[gid];
                float c2v = act ? cnew : cold;
                g_h[gid] = h2;
                g_c[gid] = c2v;
                g_hT[d * 16 + b] = hnew;
                g_xT[(1536 + d) * 16 + b] = h2;
            }
        }
        bar_sync(&g_cnt, &g_gen, NBLK, mygen);
    }

    // final vocab projection for t = 30 on all blocks
    phaseE(30, bid, NBLK);
}

// ================= launcher ==============================================
extern "C" void kernel_launch(void* const* d_in, const int* in_sizes, int n_in,
                              void* d_out, int out_size) {
    const float* enc    = (const float*)d_in[0];
    const float* encW   = (const float*)d_in[1];
    const float* encB   = (const float*)d_in[2];
    const float* decW   = (const float*)d_in[3];
    const float* decB   = (const float*)d_in[4];
    const float* fullW  = (const float*)d_in[5];
    const float* fullB  = (const float*)d_in[6];
    const float* emb    = (const float*)d_in[7];
    const float* Wih    = (const float*)d_in[8];
    const float* bih    = (const float*)d_in[9];
    const float* Whh    = (const float*)d_in[10];
    const float* bhh    = (const float*)d_in[11];
    const float* ihW    = (const float*)d_in[12];
    const float* ihB    = (const float*)d_in[13];
    const float* icW    = (const float*)d_in[14];
    const float* icB    = (const float*)d_in[15];
    const float* fbW    = (const float*)d_in[16];
    const float* fbB    = (const float*)d_in[17];
    const float* fcW    = (const float*)d_in[18];
    const float* fcB    = (const float*)d_in[19];
    const int*   capsin = (const int*)d_in[20];
    const int*   clen   = (const int*)d_in[21];
    float* out = (float*)d_out;

    katt1<<<dim3(8, 25), 256>>>(enc, encW, encB, clen);
    kstep<<<NBLK, 256>>>(enc, decW, decB, fullW, fullB, fbW, fbB, emb,
                         Wih, bih, Whh, bhh, fcW, fcB,
                         ihW, ihB, icW, icB, capsin, clen, out);
}